// round 11
// baseline (speedup 1.0000x reference)
#include <cuda_runtime.h>
#include <cuda_bf16.h>
#include <cuda_fp16.h>
#include <cstdint>

#define T_TREES 20
#define N_INT   31
#define F_DIM   128
#define TILE_M  512
#define THREADS 512            // 16 warps

// ---------------- smem layout (bytes) ----------------
#define B_STRIDE 272                       // 128 bf16 = 256B + 16B pad (ldmatrix conflict-free)
#define B_TREE   (32 * B_STRIDE)           // 8704 per tree
#define SM_B     0
#define SM_G     (T_TREES * B_TREE)                  // 174080
#define PSTR     520                                 // words per pair-column (512 rows + 8 pad)
#define SM_HB    (SM_G + 16 * PSTR * 4)              // 207360
#define SM_COEF  (SM_HB + T_TREES * 32 * 4)          // 209920
#define SMEM_TOTAL (SM_COEF + T_TREES * 16 * 16)     // 215040

__device__ __forceinline__ uint32_t smem_u32(const void* p) {
    uint32_t a;
    asm("{ .reg .u64 t; cvta.to.shared.u64 t, %1; cvt.u32.u64 %0, t; }" : "=r"(a) : "l"(p));
    return a;
}

// sigmoid(z) = 0.5*tanh(0.5*z + 0.5*bias) + 0.5  -> one MUFU.TANH
__device__ __forceinline__ float sig_half(float logit, float hb) {
    float z = fmaf(logit, 0.5f, hb);
    float th;
    asm("tanh.approx.f32 %0, %1;" : "=f"(th) : "f"(z));
    return fmaf(th, 0.5f, 0.5f);
}

#define LDSM_X4(d0, d1, d2, d3, addr) \
    asm volatile("ldmatrix.sync.aligned.m8n8.x4.shared.b16 {%0,%1,%2,%3}, [%4];" \
                 : "=r"(d0), "=r"(d1), "=r"(d2), "=r"(d3) : "r"(addr))

#define MMA_16816(c, a, b0v, b1v) \
    asm volatile("mma.sync.aligned.m16n8k16.row.col.f32.bf16.bf16.f32 " \
                 "{%0,%1,%2,%3}, {%4,%5,%6,%7}, {%8,%9}, {%0,%1,%2,%3};" \
                 : "+f"((c)[0]), "+f"((c)[1]), "+f"((c)[2]), "+f"((c)[3]) \
                 : "r"((a)[0]), "r"((a)[1]), "r"((a)[2]), "r"((a)[3]), \
                   "r"(b0v), "r"(b1v))

// ---------------------------------------------------------------------------
// One persistent kernel, 16 warps/CTA, 1 CTA/SM.
// Gates go through smem as half2 NODE PAIRS, conflict-free both directions:
//   write: word = (4nb+q)*520 + rw  -> banks q*8 + r0 (all 32 distinct)
//   read : word = j*520 + tid       -> consecutive words across lanes
// ---------------------------------------------------------------------------
__global__ __launch_bounds__(THREADS, 1)
void forest_hmma(const float* __restrict__ x,  const float* __restrict__ sw,
                 const float* __restrict__ sb, const float* __restrict__ ll,
                 const float* __restrict__ tw, const float* __restrict__ fm,
                 float* __restrict__ out, int n_tiles)
{
    extern __shared__ unsigned char smem[];
    const int tid  = threadIdx.x;
    const int lane = tid & 31;
    const int warp = tid >> 5;

    // ---------- CTA init ----------
    for (int idx = tid; idx < T_TREES * 32 * F_DIM; idx += THREADS) {
        int t = idx >> 12, n = (idx >> 7) & 31, k = idx & 127;
        float v = (n < N_INT) ? sw[(t * N_INT + n) * F_DIM + k] * fm[t * F_DIM + k] : 0.f;
        *(__nv_bfloat16*)(smem + SM_B + t * B_TREE + n * B_STRIDE + k * 2) = __float2bfloat16(v);
    }
    float* hb = (float*)(smem + SM_HB);
    for (int idx = tid; idx < T_TREES * 32; idx += THREADS) {
        int t = idx >> 5, n = idx & 31;
        hb[idx] = (n < N_INT) ? 0.5f * sb[t * N_INT + n] : 0.f;
    }
    if (tid < T_TREES) {
        int t = tid;
        float mx = tw[0];
        for (int i = 1; i < T_TREES; ++i) mx = fmaxf(mx, tw[i]);
        float s = 0.f;
        for (int i = 0; i < T_TREES; ++i) s += expf(tw[i] - mx);
        float w = expf(tw[t] - mx) / s;
        float4* cf = (float4*)(smem + SM_COEF) + t * 16;
        for (int p = 0; p < 16; ++p) {
            float a0 = ll[(t * 32 + 2 * p) * 2 + 0], b0 = ll[(t * 32 + 2 * p) * 2 + 1];
            float m0 = fmaxf(a0, b0), e0 = expf(a0 - m0), f0 = expf(b0 - m0);
            float i0 = w / (e0 + f0);
            float a1 = ll[(t * 32 + 2 * p + 1) * 2 + 0], b1 = ll[(t * 32 + 2 * p + 1) * 2 + 1];
            float m1 = fmaxf(a1, b1), e1 = expf(a1 - m1), f1 = expf(b1 - m1);
            float i1 = w / (e1 + f1);
            float4 v;
            v.x = e0 * i0; v.y = f0 * i0;
            v.z = e1 * i1 - v.x; v.w = f1 * i1 - v.y;
            cf[p] = v;
        }
    }
    __syncthreads();

    const uint32_t sBu = smem_u32(smem) + SM_B;
    const int r8 = lane & 7, gq = lane >> 3;
    const uint32_t lm_off = (uint32_t)(((gq >> 1) * 8 + r8) * B_STRIDE + (gq & 1) * 16);

    const int r0 = lane >> 2;          // frag row within 8
    const int c0 = (lane & 3) * 2;     // frag col pair
    uint32_t* sGp = (uint32_t*)(smem + SM_G);

    // ---------- tile loop ----------
    for (int tile = blockIdx.x; tile < n_tiles; tile += gridDim.x) {
        // A fragments: warp's 32 rows x K=128 -> 64 bf16x2 regs, reused for 20 trees.
        const float* xw = x + ((long)tile * TILE_M + warp * 32) * F_DIM;
        uint32_t A[2][8][4];
#pragma unroll
        for (int mb = 0; mb < 2; ++mb)
#pragma unroll
            for (int k = 0; k < 8; ++k)
#pragma unroll
                for (int j = 0; j < 4; ++j) {
                    int row = mb * 16 + r0 + 8 * (j & 1);
                    int col = k * 16 + c0 + 8 * (j >> 1);
                    float2 v = *(const float2*)(xw + row * F_DIM + col);
                    __nv_bfloat162 p = __floats2bfloat162_rn(v.x, v.y);
                    A[mb][k][j] = *(uint32_t*)&p;
                }

        float acc0 = 0.f, acc1 = 0.f;

        for (int t = 0; t < T_TREES; ++t) {
            float c[2][4][4];
#pragma unroll
            for (int i = 0; i < 32; ++i) ((float*)c)[i] = 0.f;

            const uint32_t bbase = sBu + t * B_TREE + lm_off;
#pragma unroll
            for (int k = 0; k < 8; ++k) {
                uint32_t b0, b1, b2, b3, b4, b5, b6, b7;
                LDSM_X4(b0, b1, b2, b3, bbase + k * 32);          // nodes 0..15
                LDSM_X4(b4, b5, b6, b7, bbase + k * 32 + 4352);   // nodes 16..31
#pragma unroll
                for (int mb = 0; mb < 2; ++mb) {
                    MMA_16816(c[mb][0], A[mb][k], b0, b1);
                    MMA_16816(c[mb][1], A[mb][k], b2, b3);
                    MMA_16816(c[mb][2], A[mb][k], b4, b5);
                    MMA_16816(c[mb][3], A[mb][k], b6, b7);
                }
            }

            // sigmoid + half2 pair store (conflict-free STS.32)
            const float* hbt = hb + t * 32;
            const int cp = 4 * 0 + (lane & 3);   // base pair col for nb=0
#pragma unroll
            for (int nb = 0; nb < 4; ++nb) {
                float2 h2 = *(const float2*)(hbt + nb * 8 + c0);
                uint32_t* col = sGp + (cp + 4 * nb) * PSTR;
#pragma unroll
                for (int mb = 0; mb < 2; ++mb) {
                    int rw = warp * 32 + mb * 16 + r0;
                    __half2 lo = __floats2half2_rn(sig_half(c[mb][nb][0], h2.x),
                                                   sig_half(c[mb][nb][1], h2.y));
                    __half2 hi = __floats2half2_rn(sig_half(c[mb][nb][2], h2.x),
                                                   sig_half(c[mb][nb][3], h2.y));
                    col[rw]     = *(uint32_t*)&lo;
                    col[rw + 8] = *(uint32_t*)&hi;
                }
            }
            __syncwarp();   // warp w wrote exactly rows [32w,32w+32) — warp-private

            // gates: 16 conflict-free LDS.32 hoisted into regs, then pure-FMA combine
            uint32_t gp[16];
#pragma unroll
            for (int j = 0; j < 16; ++j) gp[j] = sGp[j * PSTR + tid];
#define GATE(n) (((n) & 1) ? __high2float(*(__half2*)&gp[(n) >> 1]) \
                           : __low2float(*(__half2*)&gp[(n) >> 1]))
            const float4* cf = (const float4*)(smem + SM_COEF) + t * 16;
            float p0[16], p1[16];
#pragma unroll
            for (int i = 0; i < 16; ++i) {               // level 4: gates 15..30
                float4 cv = cf[i];
                float gi = GATE(15 + i);
                p0[i] = fmaf(gi, cv.z, cv.x);
                p1[i] = fmaf(gi, cv.w, cv.y);
            }
#pragma unroll
            for (int i = 0; i < 8; ++i) {                // level 3
                float gi = GATE(7 + i);
                p0[i] = fmaf(gi, p0[2 * i + 1] - p0[2 * i], p0[2 * i]);
                p1[i] = fmaf(gi, p1[2 * i + 1] - p1[2 * i], p1[2 * i]);
            }
#pragma unroll
            for (int i = 0; i < 4; ++i) {                // level 2
                float gi = GATE(3 + i);
                p0[i] = fmaf(gi, p0[2 * i + 1] - p0[2 * i], p0[2 * i]);
                p1[i] = fmaf(gi, p1[2 * i + 1] - p1[2 * i], p1[2 * i]);
            }
#pragma unroll
            for (int i = 0; i < 2; ++i) {                // level 1
                float gi = GATE(1 + i);
                p0[i] = fmaf(gi, p0[2 * i + 1] - p0[2 * i], p0[2 * i]);
                p1[i] = fmaf(gi, p1[2 * i + 1] - p1[2 * i], p1[2 * i]);
            }
            {
                float gi = GATE(0);                      // level 0
                acc0 += fmaf(gi, p0[1] - p0[0], p0[0]);
                acc1 += fmaf(gi, p1[1] - p1[0], p1[0]);
            }
#undef GATE
            __syncwarp();   // before next tree overwrites gates
        }

        ((float2*)out)[(long)tile * TILE_M + tid] = make_float2(acc0, acc1);
    }
}

// ---------------------------------------------------------------------------
// metadata order: x, split_weights, split_bias, leaf_logits, tree_weights,
//                 feature_masks.  output: [B,2] float32
// ---------------------------------------------------------------------------
extern "C" void kernel_launch(void* const* d_in, const int* in_sizes, int n_in,
                              void* d_out, int out_size) {
    const float* x  = (const float*)d_in[0];
    const float* sw = (const float*)d_in[1];
    const float* sb = (const float*)d_in[2];
    const float* ll = (const float*)d_in[3];
    const float* tw = (const float*)d_in[4];
    const float* fm = (const float*)d_in[5];
    float* out = (float*)d_out;

    const int B = in_sizes[0] / F_DIM;     // 131072
    const int n_tiles = B / TILE_M;        // 256

    int nsm = 148;
    cudaDeviceGetAttribute(&nsm, cudaDevAttrMultiProcessorCount, 0);

    cudaFuncSetAttribute(forest_hmma, cudaFuncAttributeMaxDynamicSharedMemorySize, SMEM_TOTAL);
    forest_hmma<<<nsm, THREADS, SMEM_TOTAL>>>(x, sw, sb, ll, tw, fm, out, n_tiles);
}

// round 12
// speedup vs baseline: 1.1483x; 1.1483x over previous
#include <cuda_runtime.h>
#include <cuda_bf16.h>
#include <cuda_fp16.h>
#include <cstdint>

#define T_TREES 20
#define N_INT   31
#define F_DIM   128
#define TILE_M  512
#define THREADS 512            // 16 warps

// ---------------- smem layout (bytes) ----------------
#define B_STRIDE 272                       // 128 bf16 = 256B + 16B pad (ldmatrix conflict-free)
#define B_TREE   (32 * B_STRIDE)           // 8704 per tree
#define SM_B     0
#define SM_G     (T_TREES * B_TREE)                  // 174080
#define PSTR     520                                 // words per pair-column (512 rows + 8 pad)
#define SM_HB    (SM_G + 16 * PSTR * 4)              // 207360: half2 bias pairs, 16/tree
#define SM_COEF  (SM_HB + T_TREES * 16 * 4)          // 208640: uint2 {base_h2, delta_h2}, 16/tree
#define SMEM_TOTAL (SM_COEF + T_TREES * 16 * 8)      // 211200

__device__ __forceinline__ uint32_t smem_u32(const void* p) {
    uint32_t a;
    asm("{ .reg .u64 t; cvta.to.shared.u64 t, %1; cvt.u32.u64 %0, t; }" : "=r"(a) : "l"(p));
    return a;
}

// packed sigmoid pair: g = 0.5*tanh(0.5*logit + hb) + 0.5   (hb = 0.5*bias)
__device__ __forceinline__ uint32_t sig2(__half2 logit, __half2 hb) {
    const __half2 H05 = __half2half2(__ushort_as_half(0x3800));   // {0.5, 0.5}
    __half2 z = __hfma2(logit, H05, hb);
    uint32_t zi = *(uint32_t*)&z, to;
    asm("tanh.approx.f16x2 %0, %1;" : "=r"(to) : "r"(zi));
    __half2 th = *(__half2*)&to;
    __half2 g = __hfma2(th, H05, H05);
    return *(uint32_t*)&g;
}

#define LDSM_X4(d0, d1, d2, d3, addr) \
    asm volatile("ldmatrix.sync.aligned.m8n8.x4.shared.b16 {%0,%1,%2,%3}, [%4];" \
                 : "=r"(d0), "=r"(d1), "=r"(d2), "=r"(d3) : "r"(addr))

#define MMA_16816(c, a, b0v, b1v) \
    asm volatile("mma.sync.aligned.m16n8k16.row.col.f32.bf16.bf16.f32 " \
                 "{%0,%1,%2,%3}, {%4,%5,%6,%7}, {%8,%9}, {%0,%1,%2,%3};" \
                 : "+f"((c)[0]), "+f"((c)[1]), "+f"((c)[2]), "+f"((c)[3]) \
                 : "r"((a)[0]), "r"((a)[1]), "r"((a)[2]), "r"((a)[3]), \
                   "r"(b0v), "r"(b1v))

// ---------------------------------------------------------------------------
// Persistent kernel, 16 warps/CTA, 1 CTA/SM. Packed-half2 epilogue:
//  - sigmoid via tanh.approx.f16x2 (2 gates / MUFU op)
//  - gate smem words = half2 node pairs (same conflict-free layout as R11)
//  - tree combine in half2, classes {c0,c1} carried per lane of the pair
// ---------------------------------------------------------------------------
__global__ __launch_bounds__(THREADS, 1)
void forest_hmma(const float* __restrict__ x,  const float* __restrict__ sw,
                 const float* __restrict__ sb, const float* __restrict__ ll,
                 const float* __restrict__ tw, const float* __restrict__ fm,
                 float* __restrict__ out, int n_tiles)
{
    extern __shared__ unsigned char smem[];
    const int tid  = threadIdx.x;
    const int lane = tid & 31;
    const int warp = tid >> 5;

    // ---------- CTA init ----------
    for (int idx = tid; idx < T_TREES * 32 * F_DIM; idx += THREADS) {
        int t = idx >> 12, n = (idx >> 7) & 31, k = idx & 127;
        float v = (n < N_INT) ? sw[(t * N_INT + n) * F_DIM + k] * fm[t * F_DIM + k] : 0.f;
        *(__nv_bfloat16*)(smem + SM_B + t * B_TREE + n * B_STRIDE + k * 2) = __float2bfloat16(v);
    }
    __half2* hb = (__half2*)(smem + SM_HB);
    for (int idx = tid; idx < T_TREES * 16; idx += THREADS) {
        int t = idx >> 4, p = idx & 15;
        int n0 = 2 * p, n1 = 2 * p + 1;
        float b0 = (n0 < N_INT) ? 0.5f * sb[t * N_INT + n0] : 0.f;
        float b1 = (n1 < N_INT) ? 0.5f * sb[t * N_INT + n1] : 0.f;
        hb[idx] = __floats2half2_rn(b0, b1);
    }
    if (tid < T_TREES) {
        int t = tid;
        float mx = tw[0];
        for (int i = 1; i < T_TREES; ++i) mx = fmaxf(mx, tw[i]);
        float s = 0.f;
        for (int i = 0; i < T_TREES; ++i) s += expf(tw[i] - mx);
        float w = expf(tw[t] - mx) / s;
        uint2* cf = (uint2*)(smem + SM_COEF) + t * 16;
        for (int p = 0; p < 16; ++p) {
            float a0 = ll[(t * 32 + 2 * p) * 2 + 0], b0 = ll[(t * 32 + 2 * p) * 2 + 1];
            float m0 = fmaxf(a0, b0), e0 = expf(a0 - m0), f0 = expf(b0 - m0);
            float i0 = w / (e0 + f0);
            float a1 = ll[(t * 32 + 2 * p + 1) * 2 + 0], b1 = ll[(t * 32 + 2 * p + 1) * 2 + 1];
            float m1 = fmaxf(a1, b1), e1 = expf(a1 - m1), f1 = expf(b1 - m1);
            float i1 = w / (e1 + f1);
            float c0l = e0 * i0, c1l = f0 * i0;
            __half2 base  = __floats2half2_rn(c0l, c1l);
            __half2 delta = __floats2half2_rn(e1 * i1 - c0l, f1 * i1 - c1l);
            uint2 v;
            v.x = *(uint32_t*)&base;
            v.y = *(uint32_t*)&delta;
            cf[p] = v;
        }
    }
    __syncthreads();

    const uint32_t sBu = smem_u32(smem) + SM_B;
    const int r8 = lane & 7, gq = lane >> 3;
    const uint32_t lm_off = (uint32_t)(((gq >> 1) * 8 + r8) * B_STRIDE + (gq & 1) * 16);

    const int r0 = lane >> 2;          // frag row within 8
    const int c0 = (lane & 3) * 2;     // frag col pair
    uint32_t* sGp = (uint32_t*)(smem + SM_G);

    // ---------- tile loop ----------
    for (int tile = blockIdx.x; tile < n_tiles; tile += gridDim.x) {
        // A fragments: warp's 32 rows x K=128 -> 64 bf16x2 regs, reused for 20 trees.
        const float* xw = x + ((long)tile * TILE_M + warp * 32) * F_DIM;
        uint32_t A[2][8][4];
#pragma unroll
        for (int mb = 0; mb < 2; ++mb)
#pragma unroll
            for (int k = 0; k < 8; ++k)
#pragma unroll
                for (int j = 0; j < 4; ++j) {
                    int row = mb * 16 + r0 + 8 * (j & 1);
                    int col = k * 16 + c0 + 8 * (j >> 1);
                    float2 v = *(const float2*)(xw + row * F_DIM + col);
                    __nv_bfloat162 p = __floats2bfloat162_rn(v.x, v.y);
                    A[mb][k][j] = *(uint32_t*)&p;
                }

        float acc0 = 0.f, acc1 = 0.f;

        for (int t = 0; t < T_TREES; ++t) {
            float c[2][4][4];
#pragma unroll
            for (int i = 0; i < 32; ++i) ((float*)c)[i] = 0.f;

            const uint32_t bbase = sBu + t * B_TREE + lm_off;
#pragma unroll
            for (int k = 0; k < 8; ++k) {
                uint32_t b0, b1, b2, b3, b4, b5, b6, b7;
                LDSM_X4(b0, b1, b2, b3, bbase + k * 32);          // nodes 0..15
                LDSM_X4(b4, b5, b6, b7, bbase + k * 32 + 4352);   // nodes 16..31
#pragma unroll
                for (int mb = 0; mb < 2; ++mb) {
                    MMA_16816(c[mb][0], A[mb][k], b0, b1);
                    MMA_16816(c[mb][1], A[mb][k], b2, b3);
                    MMA_16816(c[mb][2], A[mb][k], b4, b5);
                    MMA_16816(c[mb][3], A[mb][k], b6, b7);
                }
            }

            // packed sigmoid + conflict-free STS.32 of gate-pair words
            const __half2* hbt = (const __half2*)(smem + SM_HB) + t * 16;
#pragma unroll
            for (int nb = 0; nb < 4; ++nb) {
                int pr = nb * 4 + (lane & 3);               // pair-column index
                __half2 hbv = hbt[pr];
                uint32_t* col = sGp + pr * PSTR;
#pragma unroll
                for (int mb = 0; mb < 2; ++mb) {
                    int rw = warp * 32 + mb * 16 + r0;
                    col[rw]     = sig2(__floats2half2_rn(c[mb][nb][0], c[mb][nb][1]), hbv);
                    col[rw + 8] = sig2(__floats2half2_rn(c[mb][nb][2], c[mb][nb][3]), hbv);
                }
            }
            __syncwarp();   // warp w wrote exactly rows [32w,32w+32) — warp-private

            // gates: 16 conflict-free LDS.32, then half2 combine ({class0,class1} per lane)
            uint32_t gp[16];
#pragma unroll
            for (int j = 0; j < 16; ++j) gp[j] = sGp[j * PSTR + tid];
#define GATE2(n) (((n) & 1) ? __high2half2(*(__half2*)&gp[(n) >> 1]) \
                            : __low2half2(*(__half2*)&gp[(n) >> 1]))
            const uint2* cf = (const uint2*)(smem + SM_COEF) + t * 16;
            __half2 p[16];
#pragma unroll
            for (int i = 0; i < 16; ++i) {               // level 4: gates 15..30
                uint2 cv = cf[i];
                p[i] = __hfma2(GATE2(15 + i), *(__half2*)&cv.y, *(__half2*)&cv.x);
            }
#pragma unroll
            for (int i = 0; i < 8; ++i)                  // level 3
                p[i] = __hfma2(GATE2(7 + i), __hsub2(p[2 * i + 1], p[2 * i]), p[2 * i]);
#pragma unroll
            for (int i = 0; i < 4; ++i)                  // level 2
                p[i] = __hfma2(GATE2(3 + i), __hsub2(p[2 * i + 1], p[2 * i]), p[2 * i]);
#pragma unroll
            for (int i = 0; i < 2; ++i)                  // level 1
                p[i] = __hfma2(GATE2(1 + i), __hsub2(p[2 * i + 1], p[2 * i]), p[2 * i]);
            {
                __half2 r = __hfma2(GATE2(0), __hsub2(p[1], p[0]), p[0]);   // level 0
                acc0 += __low2float(r);
                acc1 += __high2float(r);
            }
#undef GATE2
            __syncwarp();   // before next tree overwrites gates
        }

        ((float2*)out)[(long)tile * TILE_M + tid] = make_float2(acc0, acc1);
    }
}

// ---------------------------------------------------------------------------
// metadata order: x, split_weights, split_bias, leaf_logits, tree_weights,
//                 feature_masks.  output: [B,2] float32
// ---------------------------------------------------------------------------
extern "C" void kernel_launch(void* const* d_in, const int* in_sizes, int n_in,
                              void* d_out, int out_size) {
    const float* x  = (const float*)d_in[0];
    const float* sw = (const float*)d_in[1];
    const float* sb = (const float*)d_in[2];
    const float* ll = (const float*)d_in[3];
    const float* tw = (const float*)d_in[4];
    const float* fm = (const float*)d_in[5];
    float* out = (float*)d_out;

    const int B = in_sizes[0] / F_DIM;     // 131072
    const int n_tiles = B / TILE_M;        // 256

    int nsm = 148;
    cudaDeviceGetAttribute(&nsm, cudaDevAttrMultiProcessorCount, 0);

    cudaFuncSetAttribute(forest_hmma, cudaFuncAttributeMaxDynamicSharedMemorySize, SMEM_TOTAL);
    forest_hmma<<<nsm, THREADS, SMEM_TOTAL>>>(x, sw, sb, ll, tw, fm, out, n_tiles);
}